// round 8
// baseline (speedup 1.0000x reference)
#include <cuda_runtime.h>
#include <cuda_fp16.h>

#define HWSZ (512*512)
#define HALO (42*42)
typedef unsigned long long u64;

__device__ __forceinline__ float ex2f(float x) {
    float r; asm("ex2.approx.f32 %0, %1;" : "=f"(r) : "f"(x)); return r;
}
__device__ __forceinline__ float rcpf(float x) {
    float r; asm("rcp.approx.f32 %0, %1;" : "=f"(r) : "f"(x)); return r;
}
__device__ __forceinline__ u64 pk(float a, float b) {
    u64 r; asm("mov.b64 %0, {%1,%2};" : "=l"(r) : "f"(a), "f"(b)); return r;
}
__device__ __forceinline__ u64 mul2(u64 a, u64 b) {
    u64 r; asm("mul.rn.f32x2 %0, %1, %2;" : "=l"(r) : "l"(a), "l"(b)); return r;
}
__device__ __forceinline__ u64 fma2(u64 a, u64 b, u64 c) {
    u64 r; asm("fma.rn.f32x2 %0, %1, %2, %3;" : "=l"(r) : "l"(a), "l"(b), "l"(c)); return r;
}
__device__ __forceinline__ u64 add2(u64 a, u64 b) {
    u64 r; asm("add.rn.f32x2 %0, %1, %2;" : "=l"(r) : "l"(a), "l"(b)); return r;
}

// Tile 32x32 outputs, block (32,4)=128 thr, 8 output rows/thread.
// Shared per halo site (24 B):
//   tA (16B f32): (c0, c1, c2, 1.0f) -> ulonglong2: c01/c2w pairs, no packs
//   tB ( 8B fp16): (u, u^4, u^9, u^16); u^25 = u^9*u^16 at consumer
__global__ __launch_bounds__(128, 5) void GaussPSF_kernel(
    const float* __restrict__ img,
    const float* __restrict__ psf,
    float* __restrict__ out)
{
    extern __shared__ char shraw[];
    float4* tA = reinterpret_cast<float4*>(shraw);                     // HALO+1
    uint2*  tB = reinterpret_cast<uint2*>(shraw + (HALO + 1) * 16);    // HALO+1

    const int tx = threadIdx.x;           // 0..31
    const int ty = threadIdx.y;           // 0..3
    const int tid = ty * 32 + tx;
    const int x0 = blockIdx.x * 32;
    const int y0 = blockIdx.y * 32;
    const int b  = blockIdx.z;

    const float* imb = img + (size_t)b * 3 * HWSZ;
    const float* psb = psf + (size_t)b * HWSZ;

    // ---- stage halo: EX2/RCP + power chain once per site; powers -> fp16 ----
    for (int i = tid; i < HALO; i += 128) {
        int sy = i / 42;
        int sx = i - sy * 42;
        int gy = y0 - 5 + sy;
        int gx = x0 - 5 + sx;
        float4 ra;
        uint2  rb;
        if ((unsigned)gy < 512u && (unsigned)gx < 512u) {
            int p = gy * 512 + gx;
            ra.x = imb[p];
            ra.y = imb[HWSZ + p];
            ra.z = imb[2 * HWSZ + p];
            ra.w = 1.0f;                                      // wsum rides here
            float w = psb[p];
            float t  = fmaf(w + w, w, 1e-5f);                 // 2w^2 + eps
            float u  = ex2f(-1.4426950408889634f * rcpf(t));  // u
            float u2 = u * u;
            float u4 = u2 * u2;
            float u8 = u4 * u4;
            float u9 = u8 * u;
            float u16 = u8 * u8;
            __half2 h01 = __floats2half2_rn(u, u4);
            __half2 h23 = __floats2half2_rn(u9, u16);
            rb.x = *reinterpret_cast<unsigned int*>(&h01);
            rb.y = *reinterpret_cast<unsigned int*>(&h23);
        } else {
            ra.x = 0.f; ra.y = 0.f; ra.z = 0.f; ra.w = 0.f;   // taps vanish
            rb.x = 0u;  rb.y = 0u;                            // powers -> 0
        }
        tA[i] = ra;
        tB[i] = rb;
    }
    __syncthreads();

    const ulonglong2* tA64 = reinterpret_cast<const ulonglong2*>(tA);

    // ---- 8 outputs per thread: rows y0 + ty*8 + (0..7), column x0 + tx ----
    u64 a01[8], a2w[8];
    #pragma unroll
    for (int o = 0; o < 8; ++o) { a01[o] = 0ull; a2w[o] = 0ull; }

    const int rowbase = ty * 8;

    #pragma unroll
    for (int s = 0; s < 18; ++s) {            // shared row = rowbase + s
        const int base = (rowbase + s) * 42 + tx;
        ulonglong2 av = tA64[base];           // prefetch j=0
        uint2      bv = tB[base];
        #pragma unroll
        for (int j = 0; j < 11; ++j) {
            // unconditional prefetch (arrays padded by 1 site)
            ulonglong2 an = tA64[base + j + 1];
            uint2      bn = tB[base + j + 1];

            // decode fp16 powers -> f32 (ALU pipe), broadcast pairs
            float2 f01 = __half22float2(*reinterpret_cast<__half2*>(&bv.x));
            float2 f23 = __half22float2(*reinterpret_cast<__half2*>(&bv.y));
            float u25 = f23.x * f23.y;

            u64 P[6];
            P[1] = pk(f01.x, f01.x);
            P[2] = pk(f01.y, f01.y);
            P[3] = pk(f23.x, f23.x);
            P[4] = pk(f23.y, f23.y);
            P[5] = pk(u25,  u25);

            const int dxa = (j < 5) ? (5 - j) : (j - 5);
            u64 c01 = av.x;                   // (c0,c1) — direct from LDS.128
            u64 c2w = av.y;                   // (c2,1.0)
            if (dxa != 0) {
                c01 = mul2(c01, P[dxa]);
                c2w = mul2(c2w, P[dxa]);
            }

            #pragma unroll
            for (int o = 0; o < 8; ++o) {
                const int dy  = s - 5 - o;     // compile-time after unroll
                const int dya = (dy < 0) ? -dy : dy;
                if (dya <= 5) {
                    if (dya == 0) {
                        a01[o] = add2(a01[o], c01);
                        a2w[o] = add2(a2w[o], c2w);
                    } else {
                        a01[o] = fma2(c01, P[dya], a01[o]);
                        a2w[o] = fma2(c2w, P[dya], a2w[o]);
                    }
                }
            }
            av = an; bv = bn;
        }
    }

    // ---- normalize & write ----
    float* ob = out + (size_t)b * 3 * HWSZ;
    #pragma unroll
    for (int o = 0; o < 8; ++o) {
        float o0, o1, o2, ws;
        asm("mov.b64 {%0,%1}, %2;" : "=f"(o0), "=f"(o1) : "l"(a01[o]));
        asm("mov.b64 {%0,%1}, %2;" : "=f"(o2), "=f"(ws) : "l"(a2w[o]));
        float rw = rcpf(ws);
        int y = y0 + rowbase + o;
        int p = y * 512 + x0 + tx;
        ob[p]            = o0 * rw;
        ob[HWSZ + p]     = o1 * rw;
        ob[2 * HWSZ + p] = o2 * rw;
    }
}

extern "C" void kernel_launch(void* const* d_in, const int* in_sizes, int n_in,
                              void* d_out, int out_size)
{
    const float* img = (const float*)d_in[0];   // (4,3,512,512) f32
    const float* psf = (const float*)d_in[1];   // (4,512,512)   f32
    float* out = (float*)d_out;                 // (4,3,512,512) f32

    const int smem = (HALO + 1) * 16 + (HALO + 1) * 8;   // 42360 B
    cudaFuncSetAttribute(GaussPSF_kernel,
                         cudaFuncAttributeMaxDynamicSharedMemorySize, smem);

    dim3 block(32, 4, 1);
    dim3 grid(512 / 32, 512 / 32, 4);
    GaussPSF_kernel<<<grid, block, smem>>>(img, psf, out);
}

// round 9
// speedup vs baseline: 1.0483x; 1.0483x over previous
#include <cuda_runtime.h>

#define HWSZ (512*512)
#define HALO (42*42)
typedef unsigned long long u64;

__device__ __forceinline__ float ex2f(float x) {
    float r; asm("ex2.approx.f32 %0, %1;" : "=f"(r) : "f"(x)); return r;
}
__device__ __forceinline__ float rcpf(float x) {
    float r; asm("rcp.approx.f32 %0, %1;" : "=f"(r) : "f"(x)); return r;
}
__device__ __forceinline__ u64 pk(float a, float b) {
    u64 r; asm("mov.b64 %0, {%1,%2};" : "=l"(r) : "f"(a), "f"(b)); return r;
}
__device__ __forceinline__ u64 mul2(u64 a, u64 b) {
    u64 r; asm("mul.rn.f32x2 %0, %1, %2;" : "=l"(r) : "l"(a), "l"(b)); return r;
}
__device__ __forceinline__ u64 fma2(u64 a, u64 b, u64 c) {
    u64 r; asm("fma.rn.f32x2 %0, %1, %2, %3;" : "=l"(r) : "l"(a), "l"(b), "l"(c)); return r;
}
__device__ __forceinline__ u64 add2(u64 a, u64 b) {
    u64 r; asm("add.rn.f32x2 %0, %1, %2;" : "=l"(r) : "l"(a), "l"(b)); return r;
}

// round-to-nearest bf16 (as high-16 of f32), packed manually
__device__ __forceinline__ unsigned int bf16_hi(float f) {
    return (__float_as_uint(f) + 0x8000u) >> 16;
}

// Tile 32x32 outputs, block (32,4)=128 thr, 8 output rows/thread.
// Shared per halo site (24 B):
//   tA (16B f32): (c0, c1, c2, 1.0f) -> ulonglong2: c01/c2w pairs, no packs
//   tB ( 8B bf16): (u, u^4, u^9, u^16); decode = SHF/LOP on ALU pipe;
//                  u^25 pair = mul2(P3,P4)
__global__ __launch_bounds__(128, 5) void GaussPSF_kernel(
    const float* __restrict__ img,
    const float* __restrict__ psf,
    float* __restrict__ out)
{
    extern __shared__ char shraw[];
    float4* tA = reinterpret_cast<float4*>(shraw);                     // HALO+1
    uint2*  tB = reinterpret_cast<uint2*>(shraw + (HALO + 1) * 16);    // HALO+1

    const int tx = threadIdx.x;           // 0..31
    const int ty = threadIdx.y;           // 0..3
    const int tid = ty * 32 + tx;
    const int x0 = blockIdx.x * 32;
    const int y0 = blockIdx.y * 32;
    const int b  = blockIdx.z;

    const float* imb = img + (size_t)b * 3 * HWSZ;
    const float* psb = psf + (size_t)b * HWSZ;

    // ---- stage halo: EX2/RCP + power chain once per site; powers -> bf16 ----
    for (int i = tid; i < HALO; i += 128) {
        int sy = i / 42;
        int sx = i - sy * 42;
        int gy = y0 - 5 + sy;
        int gx = x0 - 5 + sx;
        float4 ra;
        uint2  rb;
        if ((unsigned)gy < 512u && (unsigned)gx < 512u) {
            int p = gy * 512 + gx;
            ra.x = imb[p];
            ra.y = imb[HWSZ + p];
            ra.z = imb[2 * HWSZ + p];
            ra.w = 1.0f;                                      // wsum rides here
            float w = psb[p];
            float t  = fmaf(w + w, w, 1e-5f);                 // 2w^2 + eps
            float u  = ex2f(-1.4426950408889634f * rcpf(t));  // u
            float u2 = u * u;
            float u4 = u2 * u2;
            float u8 = u4 * u4;
            float u9 = u8 * u;
            float u16 = u8 * u8;
            rb.x = bf16_hi(u)  | (bf16_hi(u4)  << 16);
            rb.y = bf16_hi(u9) | (bf16_hi(u16) << 16);
        } else {
            ra.x = 0.f; ra.y = 0.f; ra.z = 0.f; ra.w = 0.f;   // taps vanish
            rb.x = 0u;  rb.y = 0u;                            // powers -> 0
        }
        tA[i] = ra;
        tB[i] = rb;
    }
    __syncthreads();

    const ulonglong2* tA64 = reinterpret_cast<const ulonglong2*>(tA);

    // ---- 8 outputs per thread: rows y0 + ty*8 + (0..7), column x0 + tx ----
    u64 a01[8], a2w[8];
    #pragma unroll
    for (int o = 0; o < 8; ++o) { a01[o] = 0ull; a2w[o] = 0ull; }

    const int rowbase = ty * 8;

    #pragma unroll
    for (int s = 0; s < 18; ++s) {            // shared row = rowbase + s
        const int base = (rowbase + s) * 42 + tx;
        ulonglong2 av = tA64[base];           // prefetch j=0
        uint2      bv = tB[base];
        #pragma unroll
        for (int j = 0; j < 11; ++j) {
            // unconditional prefetch (arrays padded by 1 site)
            ulonglong2 an = tA64[base + j + 1];
            uint2      bn = tB[base + j + 1];

            // decode bf16 powers on ALU pipe (SHF / LOP), then broadcast-pack
            float fu   = __uint_as_float(bv.x << 16);
            float fu4  = __uint_as_float(bv.x & 0xFFFF0000u);
            float fu9  = __uint_as_float(bv.y << 16);
            float fu16 = __uint_as_float(bv.y & 0xFFFF0000u);

            u64 P[6];
            P[1] = pk(fu,   fu);
            P[2] = pk(fu4,  fu4);
            P[3] = pk(fu9,  fu9);
            P[4] = pk(fu16, fu16);
            P[5] = mul2(P[3], P[4]);          // {u^25,u^25}, no pack needed

            const int dxa = (j < 5) ? (5 - j) : (j - 5);
            u64 c01 = av.x;                   // (c0,c1) — direct from LDS.128
            u64 c2w = av.y;                   // (c2,1.0)
            if (dxa != 0) {
                c01 = mul2(c01, P[dxa]);
                c2w = mul2(c2w, P[dxa]);
            }

            #pragma unroll
            for (int o = 0; o < 8; ++o) {
                const int dy  = s - 5 - o;     // compile-time after unroll
                const int dya = (dy < 0) ? -dy : dy;
                if (dya <= 5) {
                    if (dya == 0) {
                        a01[o] = add2(a01[o], c01);
                        a2w[o] = add2(a2w[o], c2w);
                    } else {
                        a01[o] = fma2(c01, P[dya], a01[o]);
                        a2w[o] = fma2(c2w, P[dya], a2w[o]);
                    }
                }
            }
            av = an; bv = bn;
        }
    }

    // ---- normalize & write ----
    float* ob = out + (size_t)b * 3 * HWSZ;
    #pragma unroll
    for (int o = 0; o < 8; ++o) {
        float o0, o1, o2, ws;
        asm("mov.b64 {%0,%1}, %2;" : "=f"(o0), "=f"(o1) : "l"(a01[o]));
        asm("mov.b64 {%0,%1}, %2;" : "=f"(o2), "=f"(ws) : "l"(a2w[o]));
        float rw = rcpf(ws);
        int y = y0 + rowbase + o;
        int p = y * 512 + x0 + tx;
        ob[p]            = o0 * rw;
        ob[HWSZ + p]     = o1 * rw;
        ob[2 * HWSZ + p] = o2 * rw;
    }
}

extern "C" void kernel_launch(void* const* d_in, const int* in_sizes, int n_in,
                              void* d_out, int out_size)
{
    const float* img = (const float*)d_in[0];   // (4,3,512,512) f32
    const float* psf = (const float*)d_in[1];   // (4,512,512)   f32
    float* out = (float*)d_out;                 // (4,3,512,512) f32

    const int smem = (HALO + 1) * 16 + (HALO + 1) * 8;   // 42360 B
    cudaFuncSetAttribute(GaussPSF_kernel,
                         cudaFuncAttributeMaxDynamicSharedMemorySize, smem);

    dim3 block(32, 4, 1);
    dim3 grid(512 / 32, 512 / 32, 4);
    GaussPSF_kernel<<<grid, block, smem>>>(img, psf, out);
}